// round 14
// baseline (speedup 1.0000x reference)
#include <cuda_runtime.h>
#include <cuda_fp16.h>
#include <cstdint>
#include <math.h>

#define BATCH 8192
#define INDIM 1024
#define HID   2048
#define KTOT  3072
#define NTOT  8192

#define BM 128
#define BN 128
#define BK 64
#define STAGES 3
#define THREADS 128
#define A_BYTES (BM * BK * 2)               // 16384
#define B_BYTES (BN * BK * 2)               // 16384
#define STAGE_BYTES (A_BYTES + B_BYTES)     // 32768
#define SMEM_BYTES (STAGES * STAGE_BYTES)   // 98304 (2 CTAs/SM -> 192KB)

#define GATES_CTAS 4096                     // 64 m-tiles x 32... (64 x 64 n-tiles)
#define RES_CTAS   1024                     // 64 m-tiles x 16 n-tiles
// prep grid partition
#define XH_BLKS  (12 * 8192)                // 98304
#define WG_BLKS  (96 * 64 * 4)              // 24576
#define WR_BLKS  (32 * 64)                  // 2048

__device__ __half g_xh [(size_t)BATCH * KTOT];   // concat(x,h) fp16
__device__ __half g_wt [(size_t)NTOT  * KTOT];   // gates weights, rows = g*HID+h, K-major
__device__ __half g_wrt[(size_t)HID   * INDIM];  // residual weights, K-major
__device__ __half g_gates[(size_t)BATCH * NTOT]; // gate preacts (fp16 scratch)
__device__ float  g_xres [(size_t)BATCH * HID];  // residual preacts (fp32)

__device__ __forceinline__ uint32_t smem_u32(const void* p) {
    uint32_t a;
    asm("{ .reg .u64 t; cvta.to.shared.u64 t, %1; cvt.u32.u64 %0, t; }" : "=r"(a) : "l"(p));
    return a;
}
__device__ __forceinline__ uint32_t swz(uint32_t o) { return o ^ ((o >> 3) & 0x70); }
__device__ __forceinline__ void cp16(uint32_t dst, const void* src) {
    asm volatile("cp.async.cg.shared.global [%0], [%1], 16;" :: "r"(dst), "l"(src));
}
#define CP_COMMIT() asm volatile("cp.async.commit_group;" ::: "memory")
#define CP_WAIT(n)  asm volatile("cp.async.wait_group %0;" :: "n"(n) : "memory")

__device__ __forceinline__ void ldsm_x4(uint32_t* d, uint32_t addr) {
    asm volatile("ldmatrix.sync.aligned.m8n8.x4.shared.b16 {%0,%1,%2,%3}, [%4];"
        : "=r"(d[0]), "=r"(d[1]), "=r"(d[2]), "=r"(d[3]) : "r"(addr));
}
__device__ __forceinline__ void mma16816(float* c, const uint32_t* a, const uint32_t* b) {
    asm volatile(
        "mma.sync.aligned.m16n8k16.row.col.f32.f16.f16.f32 "
        "{%0,%1,%2,%3}, {%4,%5,%6,%7}, {%8,%9}, {%0,%1,%2,%3};"
        : "+f"(c[0]), "+f"(c[1]), "+f"(c[2]), "+f"(c[3])
        : "r"(a[0]), "r"(a[1]), "r"(a[2]), "r"(a[3]), "r"(b[0]), "r"(b[1]));
}

// ---------------- merged pre-pass ----------------
__global__ void prep_all(const float* __restrict__ x, const float* __restrict__ h,
                         const float* __restrict__ Wg, const float* __restrict__ Wr) {
    __shared__ float t[32][33];
    int bid = blockIdx.x;

    if (bid < XH_BLKS) {
        // concat(x,h) -> fp16
        int kblk = bid % 12;
        int b = bid / 12;
        int k = kblk * 256 + threadIdx.x;
        float v = (k < INDIM) ? x[(size_t)b * INDIM + k]
                              : h[(size_t)b * HID + (k - INDIM)];
        g_xh[(size_t)b * KTOT + k] = __float2half_rn(v);
        return;
    }

    int tx = threadIdx.x & 31, ty = threadIdx.x >> 5;   // (32, 8)

    if (bid < XH_BLKS + WG_BLKS) {
        // W_gates[g][k][h] -> g_wt[g*HID+h][k]
        int tb = bid - XH_BLKS;
        int kb = tb % 96, hb = (tb / 96) % 64, g = tb / (96 * 64);
        int k0 = kb * 32, h0 = hb * 32;
        const float* src = Wg + ((size_t)g * KTOT + k0) * HID + h0;
#pragma unroll
        for (int i = 0; i < 4; i++)
            t[ty + 8 * i][tx] = src[(size_t)(ty + 8 * i) * HID + tx];
        __syncthreads();
#pragma unroll
        for (int i = 0; i < 4; i++) {
            int hh = ty + 8 * i;
            g_wt[((size_t)(g * HID + h0 + hh)) * KTOT + k0 + tx] =
                __float2half_rn(t[tx][hh]);
        }
        return;
    }

    {
        // W_res[k][h] -> g_wrt[h][k]
        int tb = bid - XH_BLKS - WG_BLKS;
        int kb = tb % 32, hb = tb / 32;
        int k0 = kb * 32, h0 = hb * 32;
        const float* src = Wr + (size_t)k0 * HID + h0;
#pragma unroll
        for (int i = 0; i < 4; i++)
            t[ty + 8 * i][tx] = src[(size_t)(ty + 8 * i) * HID + tx];
        __syncthreads();
#pragma unroll
        for (int i = 0; i < 4; i++) {
            int hh = ty + 8 * i;
            g_wrt[((size_t)(h0 + hh)) * INDIM + k0 + tx] =
                __float2half_rn(t[tx][hh]);
        }
    }
}

// ---------------- combined GEMM: gates CTAs first, residual CTAs backfill tail ----------------
__device__ __forceinline__ void load_stage(uint32_t sA, uint32_t sB,
                                           const __half* __restrict__ A,
                                           const __half* __restrict__ Bw,
                                           int m0, int n0, int k0,
                                           int lda, int ldb, int tid) {
#pragma unroll
    for (int it = 0; it < 8; it++) {             // A: 128 rows x 8 x 16B
        int i = tid + it * THREADS;
        int r = i >> 3, cg = i & 7;
        uint32_t sw = swz((uint32_t)(r * 128 + cg * 16));
        cp16(sA + sw, A + (size_t)(m0 + r) * lda + k0 + cg * 8);
    }
#pragma unroll
    for (int it = 0; it < 8; it++) {             // B: 128 rows x 8 x 16B
        int i = tid + it * THREADS;
        int r = i >> 3, cg = i & 7;
        uint32_t sw = swz((uint32_t)(r * 128 + cg * 16));
        cp16(sB + sw, Bw + (size_t)(n0 + r) * ldb + k0 + cg * 8);
    }
}

__global__ void __launch_bounds__(THREADS, 2)
gemm_all(const __half* __restrict__ A) {
    extern __shared__ char smem[];
    uint32_t sb = smem_u32(smem);
    const int tid = threadIdx.x, lane = tid & 31, wid = tid >> 5;
    const int wm = wid & 1;                 // 2 warps along M (64 rows each)
    const int wn = wid >> 1;                // 2 warps along N (64 cols each)

    const int bid = blockIdx.x;
    const bool is_gates = (bid < GATES_CTAS);
    int m0, n0, K, ldb;
    const __half* Bw;
    if (is_gates) {
        m0 = (bid & 63) * BM;               // m fastest -> L2 weight reuse per wave
        n0 = (bid >> 6) * BN;
        K = KTOT; ldb = KTOT; Bw = g_wt;
    } else {
        int rb = bid - GATES_CTAS;
        m0 = (rb & 63) * BM;
        n0 = (rb >> 6) * BN;                // 16 n-tiles
        K = INDIM; ldb = INDIM; Bw = g_wrt;
    }
    const int lda = KTOT;
    const int nch = K / BK;

    float acc[4][8][4];
#pragma unroll
    for (int mi = 0; mi < 4; mi++)
#pragma unroll
        for (int ni = 0; ni < 8; ni++)
#pragma unroll
            for (int e = 0; e < 4; e++) acc[mi][ni][e] = 0.0f;

#pragma unroll
    for (int s = 0; s < STAGES - 1; s++) {
        load_stage(sb + s * STAGE_BYTES, sb + s * STAGE_BYTES + A_BYTES,
                   A, Bw, m0, n0, s * BK, lda, ldb, tid);
        CP_COMMIT();
    }

    for (int c = 0; c < nch; c++) {
        CP_WAIT(STAGES - 2);
        __syncthreads();

        int cl = c + STAGES - 1;
        if (cl < nch) {
            int s = cl % STAGES;
            load_stage(sb + s * STAGE_BYTES, sb + s * STAGE_BYTES + A_BYTES,
                       A, Bw, m0, n0, cl * BK, lda, ldb, tid);
        }
        CP_COMMIT();

        uint32_t sA = sb + (c % STAGES) * STAGE_BYTES;
        uint32_t sB = sA + A_BYTES;

#pragma unroll
        for (int ks = 0; ks < 4; ks++) {
            uint32_t af[4][4];
            {
                int ra = lane & 15;
                int kg = ks * 2 + (lane >> 4);
#pragma unroll
                for (int mi = 0; mi < 4; mi++) {
                    uint32_t off = (uint32_t)((wm * 64 + mi * 16 + ra) * 128 + kg * 16);
                    ldsm_x4(af[mi], sA + swz(off));
                }
            }
            uint32_t bf[8][2];
            {
                int rb2 = (lane & 7) + ((lane >> 4) << 3);
                int kg = ks * 2 + ((lane >> 3) & 1);
#pragma unroll
                for (int nq = 0; nq < 4; nq++) {
                    uint32_t t[4];
                    uint32_t off = (uint32_t)((wn * 64 + nq * 16 + rb2) * 128 + kg * 16);
                    ldsm_x4(t, sB + swz(off));
                    bf[nq * 2][0] = t[0]; bf[nq * 2][1] = t[1];
                    bf[nq * 2 + 1][0] = t[2]; bf[nq * 2 + 1][1] = t[3];
                }
            }
#pragma unroll
            for (int mi = 0; mi < 4; mi++)
#pragma unroll
                for (int ni = 0; ni < 8; ni++)
                    mma16816(acc[mi][ni], af[mi], bf[ni]);
        }
    }

    const int gid = lane >> 2, tq = lane & 3;
    if (is_gates) {
        // fp16 store (gates scratch), ldC = NTOT
#pragma unroll
        for (int mi = 0; mi < 4; mi++) {
#pragma unroll
            for (int ni = 0; ni < 8; ni++) {
                int m = m0 + wm * 64 + mi * 16 + gid;
                int n = n0 + wn * 64 + ni * 8 + tq * 2;
                *(__half2*)&g_gates[(size_t)m * NTOT + n] =
                    __floats2half2_rn(acc[mi][ni][0], acc[mi][ni][1]);
                *(__half2*)&g_gates[(size_t)(m + 8) * NTOT + n] =
                    __floats2half2_rn(acc[mi][ni][2], acc[mi][ni][3]);
            }
        }
    } else {
        // fp32 store (residual scratch), ldC = HID
#pragma unroll
        for (int mi = 0; mi < 4; mi++) {
#pragma unroll
            for (int ni = 0; ni < 8; ni++) {
                int m = m0 + wm * 64 + mi * 16 + gid;
                int n = n0 + wn * 64 + ni * 8 + tq * 2;
                *(float2*)&g_xres[(size_t)m * HID + n]       = make_float2(acc[mi][ni][0], acc[mi][ni][1]);
                *(float2*)&g_xres[(size_t)(m + 8) * HID + n] = make_float2(acc[mi][ni][2], acc[mi][ni][3]);
            }
        }
    }
}

// ---------------- elementwise LSTM epilogue (2 cells / thread) ----------------
__global__ void lstm_epilogue(const float* __restrict__ c_prev,
                              const float* __restrict__ bg,
                              const float* __restrict__ br,
                              float* __restrict__ out) {
    int hcol = (blockIdx.x * 256 + threadIdx.x) * 2;   // grid.x = HID/512 = 4
    int b = blockIdx.y;
    const __half* grow = g_gates + (size_t)b * NTOT;

    float2 pi = __half22float2(*(const __half2*)&grow[hcol]);
    float2 pf = __half22float2(*(const __half2*)&grow[HID + hcol]);
    float2 po = __half22float2(*(const __half2*)&grow[2 * HID + hcol]);
    float2 pc = __half22float2(*(const __half2*)&grow[3 * HID + hcol]);

    float2 bi = *(const float2*)&bg[hcol];
    float2 bf = *(const float2*)&bg[2048 + hcol];
    float2 bo = *(const float2*)&bg[4096 + hcol];
    float2 bc = *(const float2*)&bg[6144 + hcol];

    float2 cp = *(const float2*)&c_prev[(size_t)b * HID + hcol];
    float2 xr = *(const float2*)&g_xres[(size_t)b * HID + hcol];
    float2 brv = *(const float2*)&br[hcol];

    float2 ht, ct;
    {
        float iv = 1.0f / (1.0f + __expf(-(pi.x + bi.x)));
        float fv = 1.0f / (1.0f + __expf(-(pf.x + bf.x)));
        float ov = 1.0f / (1.0f + __expf(-(po.x + bo.x)));
        float ch = tanhf(pc.x + bc.x);
        ct.x = fv * cp.x + iv * ch;
        ht.x = ov * tanhf(ct.x) + xr.x + brv.x;
    }
    {
        float iv = 1.0f / (1.0f + __expf(-(pi.y + bi.y)));
        float fv = 1.0f / (1.0f + __expf(-(pf.y + bf.y)));
        float ov = 1.0f / (1.0f + __expf(-(po.y + bo.y)));
        float ch = tanhf(pc.y + bc.y);
        ct.y = fv * cp.y + iv * ch;
        ht.y = ov * tanhf(ct.y) + xr.y + brv.y;
    }

    *(float2*)&out[(size_t)b * HID + hcol] = ht;
    *(float2*)&out[(size_t)BATCH * HID + (size_t)b * HID + hcol] = ct;
}

extern "C" void kernel_launch(void* const* d_in, const int* in_sizes, int n_in,
                              void* d_out, int out_size) {
    const float* x  = (const float*)d_in[0];
    const float* h  = (const float*)d_in[1];
    const float* c  = (const float*)d_in[2];
    const float* Wg = (const float*)d_in[3];
    const float* bg = (const float*)d_in[4];
    const float* Wr = (const float*)d_in[5];
    const float* br = (const float*)d_in[6];
    float* out = (float*)d_out;

    prep_all<<<XH_BLKS + WG_BLKS + WR_BLKS, 256>>>(x, h, Wg, Wr);

    cudaFuncSetAttribute(gemm_all, cudaFuncAttributeMaxDynamicSharedMemorySize, SMEM_BYTES);

    __half* xh;  cudaGetSymbolAddress((void**)&xh,  g_xh);

    // gates CTAs [0, 4096) + residual CTAs [4096, 5120) in one launch
    gemm_all<<<GATES_CTAS + RES_CTAS, THREADS, SMEM_BYTES>>>(xh);

    lstm_epilogue<<<dim3(HID / 512, BATCH), 256>>>(c, bg, br, out);

    (void)in_sizes; (void)n_in; (void)out_size;
}

// round 15
// speedup vs baseline: 1.0465x; 1.0465x over previous
#include <cuda_runtime.h>
#include <cuda_fp16.h>
#include <cstdint>
#include <math.h>

#define BATCH 8192
#define INDIM 1024
#define HID   2048
#define KTOT  3072
#define NTOT  8192

#define BM 128
#define BN 128
#define BK 64
#define STAGES 3
#define THREADS 128
#define A_BYTES (BM * BK * 2)               // 16384
#define B_BYTES (BN * BK * 2)               // 16384
#define STAGE_BYTES (A_BYTES + B_BYTES)     // 32768
#define SMEM_BYTES (STAGES * STAGE_BYTES)   // 98304 (2 CTAs/SM -> 192KB)

#define GATES_CTAS 4096                     // 64 m-tiles x 64 n-tiles
#define RES_CTAS   1024                     // 64 m-tiles x 16 n-tiles

// prep grid partition (256-thread blocks)
#define XH_BLKS  12288                      // 8192*3072 / (256*8)
#define WG_BLKS  (48 * 32 * 4)              // 6144: 64x64 tiles over [3072,2048] x 4 gates
#define WR_BLKS  (16 * 32)                  // 512:  64x64 tiles over [1024,2048]

__device__ __half g_xh [(size_t)BATCH * KTOT];   // concat(x,h) fp16
__device__ __half g_wt [(size_t)NTOT  * KTOT];   // gates weights, rows = g*HID+h, K-major
__device__ __half g_wrt[(size_t)HID   * INDIM];  // residual weights, K-major
__device__ __half g_gates[(size_t)BATCH * NTOT]; // gate preacts (fp16 scratch)
__device__ float  g_xres [(size_t)BATCH * HID];  // residual preacts (fp32)

__device__ __forceinline__ uint32_t smem_u32(const void* p) {
    uint32_t a;
    asm("{ .reg .u64 t; cvta.to.shared.u64 t, %1; cvt.u32.u64 %0, t; }" : "=r"(a) : "l"(p));
    return a;
}
__device__ __forceinline__ uint32_t swz(uint32_t o) { return o ^ ((o >> 3) & 0x70); }
__device__ __forceinline__ void cp16(uint32_t dst, const void* src) {
    asm volatile("cp.async.cg.shared.global [%0], [%1], 16;" :: "r"(dst), "l"(src));
}
#define CP_COMMIT() asm volatile("cp.async.commit_group;" ::: "memory")
#define CP_WAIT(n)  asm volatile("cp.async.wait_group %0;" :: "n"(n) : "memory")

__device__ __forceinline__ void ldsm_x4(uint32_t* d, uint32_t addr) {
    asm volatile("ldmatrix.sync.aligned.m8n8.x4.shared.b16 {%0,%1,%2,%3}, [%4];"
        : "=r"(d[0]), "=r"(d[1]), "=r"(d[2]), "=r"(d[3]) : "r"(addr));
}
__device__ __forceinline__ void mma16816(float* c, const uint32_t* a, const uint32_t* b) {
    asm volatile(
        "mma.sync.aligned.m16n8k16.row.col.f32.f16.f16.f32 "
        "{%0,%1,%2,%3}, {%4,%5,%6,%7}, {%8,%9}, {%0,%1,%2,%3};"
        : "+f"(c[0]), "+f"(c[1]), "+f"(c[2]), "+f"(c[3])
        : "r"(a[0]), "r"(a[1]), "r"(a[2]), "r"(a[3]), "r"(b[0]), "r"(b[1]));
}

// ---------------- merged pre-pass (vectorized) ----------------
__global__ void prep_all(const float* __restrict__ x, const float* __restrict__ h,
                         const float* __restrict__ Wg, const float* __restrict__ Wr) {
    __shared__ float t[64][65];
    int bid = blockIdx.x;
    int tid = threadIdx.x;

    if (bid < XH_BLKS) {
        // concat(x,h) -> fp16, 8 elems / thread, 16B packed store
        size_t idx = ((size_t)bid * 256 + tid) * 8;
        int b = (int)(idx / KTOT);
        int k = (int)(idx % KTOT);
        const float* src = (k < INDIM) ? (x + (size_t)b * INDIM + k)
                                       : (h + (size_t)b * HID + (k - INDIM));
        float4 v0 = *(const float4*)src;
        float4 v1 = *(const float4*)(src + 4);
        __half2 o[4];
        o[0] = __floats2half2_rn(v0.x, v0.y);
        o[1] = __floats2half2_rn(v0.z, v0.w);
        o[2] = __floats2half2_rn(v1.x, v1.y);
        o[3] = __floats2half2_rn(v1.z, v1.w);
        *(uint4*)&g_xh[idx] = *(uint4*)o;
        return;
    }

    // 64x64 transpose tiles
    const float* src;
    __half* dstbase;
    int k0, h0, dst_ld;
    if (bid < XH_BLKS + WG_BLKS) {
        int tb = bid - XH_BLKS;
        int kb = tb % 48, hb = (tb / 48) % 32, g = tb / (48 * 32);
        k0 = kb * 64; h0 = hb * 64;
        src = Wg + ((size_t)g * KTOT + k0) * HID + h0;
        dstbase = g_wt + (size_t)g * HID * KTOT;
        dst_ld = KTOT;
    } else {
        int tb = bid - XH_BLKS - WG_BLKS;
        int kb = tb % 16, hb = tb / 16;
        k0 = kb * 64; h0 = hb * 64;
        src = Wr + (size_t)k0 * HID + h0;
        dstbase = g_wrt;
        dst_ld = INDIM;
    }

    // load 64x64 fp32 tile: 64 threads per row, 4 rows per pass
    {
        int col = tid & 63;
        int rb = tid >> 6;          // 0..3
#pragma unroll
        for (int i = 0; i < 16; i++) {
            int row = i * 4 + rb;
            t[row][col] = src[(size_t)row * HID + col];
        }
    }
    __syncthreads();

    // write transposed as fp16, half2 stores (k contiguous)
    {
        int a = tid & 31;           // k-pair index: k = 2a, 2a+1
        int hb2 = tid >> 5;         // 0..7
#pragma unroll
        for (int i = 0; i < 8; i++) {
            int hh = i * 8 + hb2;
            __half2 v = __floats2half2_rn(t[2 * a][hh], t[2 * a + 1][hh]);
            *(__half2*)&dstbase[(size_t)(h0 + hh) * dst_ld + k0 + 2 * a] = v;
        }
    }
}

// ---------------- combined GEMM: gates CTAs + residual CTAs ----------------
__device__ __forceinline__ void load_stage(uint32_t sA, uint32_t sB,
                                           const __half* __restrict__ A,
                                           const __half* __restrict__ Bw,
                                           int m0, int n0, int k0,
                                           int lda, int ldb, int tid) {
#pragma unroll
    for (int it = 0; it < 8; it++) {             // A: 128 rows x 8 x 16B
        int i = tid + it * THREADS;
        int r = i >> 3, cg = i & 7;
        uint32_t sw = swz((uint32_t)(r * 128 + cg * 16));
        cp16(sA + sw, A + (size_t)(m0 + r) * lda + k0 + cg * 8);
    }
#pragma unroll
    for (int it = 0; it < 8; it++) {             // B: 128 rows x 8 x 16B
        int i = tid + it * THREADS;
        int r = i >> 3, cg = i & 7;
        uint32_t sw = swz((uint32_t)(r * 128 + cg * 16));
        cp16(sB + sw, Bw + (size_t)(n0 + r) * ldb + k0 + cg * 8);
    }
}

__global__ void __launch_bounds__(THREADS, 2)
gemm_all(const __half* __restrict__ A) {
    extern __shared__ char smem[];
    uint32_t sb = smem_u32(smem);
    const int tid = threadIdx.x, lane = tid & 31, wid = tid >> 5;
    const int wm = wid & 1;                 // 2 warps along M (64 rows each)
    const int wn = wid >> 1;                // 2 warps along N (64 cols each)

    const int bid = blockIdx.x;
    const bool is_gates = (bid < GATES_CTAS);
    int m0, n0, K, ldb;
    const __half* Bw;
    if (is_gates) {
        m0 = (bid & 63) * BM;               // m fastest -> L2 weight reuse per wave
        n0 = (bid >> 6) * BN;
        K = KTOT; ldb = KTOT; Bw = g_wt;
    } else {
        int rb = bid - GATES_CTAS;
        m0 = (rb & 63) * BM;
        n0 = (rb >> 6) * BN;                // 16 n-tiles
        K = INDIM; ldb = INDIM; Bw = g_wrt;
    }
    const int lda = KTOT;
    const int nch = K / BK;

    float acc[4][8][4];
#pragma unroll
    for (int mi = 0; mi < 4; mi++)
#pragma unroll
        for (int ni = 0; ni < 8; ni++)
#pragma unroll
            for (int e = 0; e < 4; e++) acc[mi][ni][e] = 0.0f;

#pragma unroll
    for (int s = 0; s < STAGES - 1; s++) {
        load_stage(sb + s * STAGE_BYTES, sb + s * STAGE_BYTES + A_BYTES,
                   A, Bw, m0, n0, s * BK, lda, ldb, tid);
        CP_COMMIT();
    }

    for (int c = 0; c < nch; c++) {
        CP_WAIT(STAGES - 2);
        __syncthreads();

        int cl = c + STAGES - 1;
        if (cl < nch) {
            int s = cl % STAGES;
            load_stage(sb + s * STAGE_BYTES, sb + s * STAGE_BYTES + A_BYTES,
                       A, Bw, m0, n0, cl * BK, lda, ldb, tid);
        }
        CP_COMMIT();

        uint32_t sA = sb + (c % STAGES) * STAGE_BYTES;
        uint32_t sB = sA + A_BYTES;

#pragma unroll
        for (int ks = 0; ks < 4; ks++) {
            uint32_t af[4][4];
            {
                int ra = lane & 15;
                int kg = ks * 2 + (lane >> 4);
#pragma unroll
                for (int mi = 0; mi < 4; mi++) {
                    uint32_t off = (uint32_t)((wm * 64 + mi * 16 + ra) * 128 + kg * 16);
                    ldsm_x4(af[mi], sA + swz(off));
                }
            }
            uint32_t bf[8][2];
            {
                int rb2 = (lane & 7) + ((lane >> 4) << 3);
                int kg = ks * 2 + ((lane >> 3) & 1);
#pragma unroll
                for (int nq = 0; nq < 4; nq++) {
                    uint32_t t4[4];
                    uint32_t off = (uint32_t)((wn * 64 + nq * 16 + rb2) * 128 + kg * 16);
                    ldsm_x4(t4, sB + swz(off));
                    bf[nq * 2][0] = t4[0]; bf[nq * 2][1] = t4[1];
                    bf[nq * 2 + 1][0] = t4[2]; bf[nq * 2 + 1][1] = t4[3];
                }
            }
#pragma unroll
            for (int mi = 0; mi < 4; mi++)
#pragma unroll
                for (int ni = 0; ni < 8; ni++)
                    mma16816(acc[mi][ni], af[mi], bf[ni]);
        }
    }

    const int gid = lane >> 2, tq = lane & 3;
    if (is_gates) {
#pragma unroll
        for (int mi = 0; mi < 4; mi++) {
#pragma unroll
            for (int ni = 0; ni < 8; ni++) {
                int m = m0 + wm * 64 + mi * 16 + gid;
                int n = n0 + wn * 64 + ni * 8 + tq * 2;
                *(__half2*)&g_gates[(size_t)m * NTOT + n] =
                    __floats2half2_rn(acc[mi][ni][0], acc[mi][ni][1]);
                *(__half2*)&g_gates[(size_t)(m + 8) * NTOT + n] =
                    __floats2half2_rn(acc[mi][ni][2], acc[mi][ni][3]);
            }
        }
    } else {
#pragma unroll
        for (int mi = 0; mi < 4; mi++) {
#pragma unroll
            for (int ni = 0; ni < 8; ni++) {
                int m = m0 + wm * 64 + mi * 16 + gid;
                int n = n0 + wn * 64 + ni * 8 + tq * 2;
                *(float2*)&g_xres[(size_t)m * HID + n]       = make_float2(acc[mi][ni][0], acc[mi][ni][1]);
                *(float2*)&g_xres[(size_t)(m + 8) * HID + n] = make_float2(acc[mi][ni][2], acc[mi][ni][3]);
            }
        }
    }
}

// ---------------- elementwise LSTM epilogue (2 cells / thread) ----------------
__global__ void lstm_epilogue(const float* __restrict__ c_prev,
                              const float* __restrict__ bg,
                              const float* __restrict__ br,
                              float* __restrict__ out) {
    int hcol = (blockIdx.x * 256 + threadIdx.x) * 2;   // grid.x = HID/512 = 4
    int b = blockIdx.y;
    const __half* grow = g_gates + (size_t)b * NTOT;

    float2 pi = __half22float2(*(const __half2*)&grow[hcol]);
    float2 pf = __half22float2(*(const __half2*)&grow[HID + hcol]);
    float2 po = __half22float2(*(const __half2*)&grow[2 * HID + hcol]);
    float2 pc = __half22float2(*(const __half2*)&grow[3 * HID + hcol]);

    float2 bi = *(const float2*)&bg[hcol];
    float2 bf = *(const float2*)&bg[2048 + hcol];
    float2 bo = *(const float2*)&bg[4096 + hcol];
    float2 bc = *(const float2*)&bg[6144 + hcol];

    float2 cp = *(const float2*)&c_prev[(size_t)b * HID + hcol];
    float2 xr = *(const float2*)&g_xres[(size_t)b * HID + hcol];
    float2 brv = *(const float2*)&br[hcol];

    float2 ht, ct;
    {
        float iv = 1.0f / (1.0f + __expf(-(pi.x + bi.x)));
        float fv = 1.0f / (1.0f + __expf(-(pf.x + bf.x)));
        float ov = 1.0f / (1.0f + __expf(-(po.x + bo.x)));
        float ch = tanhf(pc.x + bc.x);
        ct.x = fv * cp.x + iv * ch;
        ht.x = ov * tanhf(ct.x) + xr.x + brv.x;
    }
    {
        float iv = 1.0f / (1.0f + __expf(-(pi.y + bi.y)));
        float fv = 1.0f / (1.0f + __expf(-(pf.y + bf.y)));
        float ov = 1.0f / (1.0f + __expf(-(po.y + bo.y)));
        float ch = tanhf(pc.y + bc.y);
        ct.y = fv * cp.y + iv * ch;
        ht.y = ov * tanhf(ct.y) + xr.y + brv.y;
    }

    *(float2*)&out[(size_t)b * HID + hcol] = ht;
    *(float2*)&out[(size_t)BATCH * HID + (size_t)b * HID + hcol] = ct;
}

extern "C" void kernel_launch(void* const* d_in, const int* in_sizes, int n_in,
                              void* d_out, int out_size) {
    const float* x  = (const float*)d_in[0];
    const float* h  = (const float*)d_in[1];
    const float* c  = (const float*)d_in[2];
    const float* Wg = (const float*)d_in[3];
    const float* bg = (const float*)d_in[4];
    const float* Wr = (const float*)d_in[5];
    const float* br = (const float*)d_in[6];
    float* out = (float*)d_out;

    prep_all<<<XH_BLKS + WG_BLKS + WR_BLKS, 256>>>(x, h, Wg, Wr);

    cudaFuncSetAttribute(gemm_all, cudaFuncAttributeMaxDynamicSharedMemorySize, SMEM_BYTES);

    __half* xh;  cudaGetSymbolAddress((void**)&xh,  g_xh);

    // gates CTAs [0, 4096) + residual CTAs [4096, 5120) in one launch
    gemm_all<<<GATES_CTAS + RES_CTAS, THREADS, SMEM_BYTES>>>(xh);

    lstm_epilogue<<<dim3(HID / 512, BATCH), 256>>>(c, bg, br, out);

    (void)in_sizes; (void)n_in; (void)out_size;
}

// round 16
// speedup vs baseline: 1.0577x; 1.0106x over previous
#include <cuda_runtime.h>
#include <cuda_fp16.h>
#include <cstdint>
#include <math.h>

#define BATCH 8192
#define INDIM 1024
#define HID   2048
#define KTOT  3072
#define NTOT  8192

#define BM 128
#define BN 128
#define BK 64
#define STAGES 3
#define THREADS 128
#define A_BYTES (BM * BK * 2)               // 16384
#define B_BYTES (BN * BK * 2)               // 16384
#define STAGE_BYTES (A_BYTES + B_BYTES)     // 32768
#define SMEM_BYTES (STAGES * STAGE_BYTES)   // 98304 (2 CTAs/SM -> 192KB)

#define GATES_CTAS 4096                     // 64 m-tiles x 64 n-tiles
#define RES_CTAS   1024                     // 64 m-tiles x 16 n-tiles

// prep grid partition (256-thread blocks)
#define XH_BLKS  12288                      // 8192*3072 / (256*8)
#define WG_BLKS  (48 * 32 * 4)              // 6144: 64x64 tiles over [3072,2048] x 4 gates
#define WR_BLKS  (16 * 32)                  // 512:  64x64 tiles over [1024,2048]

__device__ __half g_xh [(size_t)BATCH * KTOT];   // concat(x,h) fp16
__device__ __half g_wt [(size_t)NTOT  * KTOT];   // gates weights, rows = g*HID+h, K-major
__device__ __half g_wrt[(size_t)HID   * INDIM];  // residual weights, K-major
__device__ __half g_gates[(size_t)BATCH * NTOT]; // gate preacts (fp16 scratch)
__device__ __half g_xresh[(size_t)BATCH * HID];  // residual preacts (fp16 scratch)

__device__ __forceinline__ uint32_t smem_u32(const void* p) {
    uint32_t a;
    asm("{ .reg .u64 t; cvta.to.shared.u64 t, %1; cvt.u32.u64 %0, t; }" : "=r"(a) : "l"(p));
    return a;
}
__device__ __forceinline__ uint32_t swz(uint32_t o) { return o ^ ((o >> 3) & 0x70); }
__device__ __forceinline__ void cp16(uint32_t dst, const void* src) {
    asm volatile("cp.async.cg.shared.global [%0], [%1], 16;" :: "r"(dst), "l"(src));
}
#define CP_COMMIT() asm volatile("cp.async.commit_group;" ::: "memory")
#define CP_WAIT(n)  asm volatile("cp.async.wait_group %0;" :: "n"(n) : "memory")

__device__ __forceinline__ void ldsm_x4(uint32_t* d, uint32_t addr) {
    asm volatile("ldmatrix.sync.aligned.m8n8.x4.shared.b16 {%0,%1,%2,%3}, [%4];"
        : "=r"(d[0]), "=r"(d[1]), "=r"(d[2]), "=r"(d[3]) : "r"(addr));
}
__device__ __forceinline__ void mma16816(float* c, const uint32_t* a, const uint32_t* b) {
    asm volatile(
        "mma.sync.aligned.m16n8k16.row.col.f32.f16.f16.f32 "
        "{%0,%1,%2,%3}, {%4,%5,%6,%7}, {%8,%9}, {%0,%1,%2,%3};"
        : "+f"(c[0]), "+f"(c[1]), "+f"(c[2]), "+f"(c[3])
        : "r"(a[0]), "r"(a[1]), "r"(a[2]), "r"(a[3]), "r"(b[0]), "r"(b[1]));
}

// ---------------- merged pre-pass (vectorized) ----------------
__global__ void prep_all(const float* __restrict__ x, const float* __restrict__ h,
                         const float* __restrict__ Wg, const float* __restrict__ Wr) {
    __shared__ float t[64][65];
    int bid = blockIdx.x;
    int tid = threadIdx.x;

    if (bid < XH_BLKS) {
        // concat(x,h) -> fp16, 8 elems / thread, 16B packed store
        size_t idx = ((size_t)bid * 256 + tid) * 8;
        int b = (int)(idx / KTOT);
        int k = (int)(idx % KTOT);
        const float* src = (k < INDIM) ? (x + (size_t)b * INDIM + k)
                                       : (h + (size_t)b * HID + (k - INDIM));
        float4 v0 = *(const float4*)src;
        float4 v1 = *(const float4*)(src + 4);
        __half2 o[4];
        o[0] = __floats2half2_rn(v0.x, v0.y);
        o[1] = __floats2half2_rn(v0.z, v0.w);
        o[2] = __floats2half2_rn(v1.x, v1.y);
        o[3] = __floats2half2_rn(v1.z, v1.w);
        *(uint4*)&g_xh[idx] = *(uint4*)o;
        return;
    }

    // 64x64 transpose tiles
    const float* src;
    __half* dstbase;
    int k0, h0, dst_ld;
    if (bid < XH_BLKS + WG_BLKS) {
        int tb = bid - XH_BLKS;
        int kb = tb % 48, hb = (tb / 48) % 32, g = tb / (48 * 32);
        k0 = kb * 64; h0 = hb * 64;
        src = Wg + ((size_t)g * KTOT + k0) * HID + h0;
        dstbase = g_wt + (size_t)g * HID * KTOT;
        dst_ld = KTOT;
    } else {
        int tb = bid - XH_BLKS - WG_BLKS;
        int kb = tb % 16, hb = tb / 16;
        k0 = kb * 64; h0 = hb * 64;
        src = Wr + (size_t)k0 * HID + h0;
        dstbase = g_wrt;
        dst_ld = INDIM;
    }

    // load 64x64 fp32 tile: 64 threads per row, 4 rows per pass
    {
        int col = tid & 63;
        int rb = tid >> 6;          // 0..3
#pragma unroll
        for (int i = 0; i < 16; i++) {
            int row = i * 4 + rb;
            t[row][col] = src[(size_t)row * HID + col];
        }
    }
    __syncthreads();

    // write transposed as fp16, half2 stores (k contiguous)
    {
        int a = tid & 31;           // k-pair index: k = 2a, 2a+1
        int hb2 = tid >> 5;         // 0..7
#pragma unroll
        for (int i = 0; i < 8; i++) {
            int hh = i * 8 + hb2;
            __half2 v = __floats2half2_rn(t[2 * a][hh], t[2 * a + 1][hh]);
            *(__half2*)&dstbase[(size_t)(h0 + hh) * dst_ld + k0 + 2 * a] = v;
        }
    }
}

// ---------------- combined GEMM: gates CTAs + residual CTAs ----------------
__device__ __forceinline__ void load_stage(uint32_t sA, uint32_t sB,
                                           const __half* __restrict__ A,
                                           const __half* __restrict__ Bw,
                                           int m0, int n0, int k0,
                                           int lda, int ldb, int tid) {
#pragma unroll
    for (int it = 0; it < 8; it++) {             // A: 128 rows x 8 x 16B
        int i = tid + it * THREADS;
        int r = i >> 3, cg = i & 7;
        uint32_t sw = swz((uint32_t)(r * 128 + cg * 16));
        cp16(sA + sw, A + (size_t)(m0 + r) * lda + k0 + cg * 8);
    }
#pragma unroll
    for (int it = 0; it < 8; it++) {             // B: 128 rows x 8 x 16B
        int i = tid + it * THREADS;
        int r = i >> 3, cg = i & 7;
        uint32_t sw = swz((uint32_t)(r * 128 + cg * 16));
        cp16(sB + sw, Bw + (size_t)(n0 + r) * ldb + k0 + cg * 8);
    }
}

__global__ void __launch_bounds__(THREADS, 2)
gemm_all(const __half* __restrict__ A) {
    extern __shared__ char smem[];
    uint32_t sb = smem_u32(smem);
    const int tid = threadIdx.x, lane = tid & 31, wid = tid >> 5;
    const int wm = wid & 1;                 // 2 warps along M (64 rows each)
    const int wn = wid >> 1;                // 2 warps along N (64 cols each)

    const int bid = blockIdx.x;
    const bool is_gates = (bid < GATES_CTAS);
    int m0, n0, K, ldb;
    const __half* Bw;
    if (is_gates) {
        m0 = (bid & 63) * BM;               // m fastest -> L2 weight reuse per wave
        n0 = (bid >> 6) * BN;
        K = KTOT; ldb = KTOT; Bw = g_wt;
    } else {
        int rb = bid - GATES_CTAS;
        m0 = (rb & 63) * BM;
        n0 = (rb >> 6) * BN;                // 16 n-tiles
        K = INDIM; ldb = INDIM; Bw = g_wrt;
    }
    const int lda = KTOT;
    const int nch = K / BK;

    float acc[4][8][4];
#pragma unroll
    for (int mi = 0; mi < 4; mi++)
#pragma unroll
        for (int ni = 0; ni < 8; ni++)
#pragma unroll
            for (int e = 0; e < 4; e++) acc[mi][ni][e] = 0.0f;

#pragma unroll
    for (int s = 0; s < STAGES - 1; s++) {
        load_stage(sb + s * STAGE_BYTES, sb + s * STAGE_BYTES + A_BYTES,
                   A, Bw, m0, n0, s * BK, lda, ldb, tid);
        CP_COMMIT();
    }

    for (int c = 0; c < nch; c++) {
        CP_WAIT(STAGES - 2);
        __syncthreads();

        int cl = c + STAGES - 1;
        if (cl < nch) {
            int s = cl % STAGES;
            load_stage(sb + s * STAGE_BYTES, sb + s * STAGE_BYTES + A_BYTES,
                       A, Bw, m0, n0, cl * BK, lda, ldb, tid);
        }
        CP_COMMIT();

        uint32_t sA = sb + (c % STAGES) * STAGE_BYTES;
        uint32_t sB = sA + A_BYTES;

#pragma unroll
        for (int ks = 0; ks < 4; ks++) {
            uint32_t af[4][4];
            {
                int ra = lane & 15;
                int kg = ks * 2 + (lane >> 4);
#pragma unroll
                for (int mi = 0; mi < 4; mi++) {
                    uint32_t off = (uint32_t)((wm * 64 + mi * 16 + ra) * 128 + kg * 16);
                    ldsm_x4(af[mi], sA + swz(off));
                }
            }
            uint32_t bf[8][2];
            {
                int rb2 = (lane & 7) + ((lane >> 4) << 3);
                int kg = ks * 2 + ((lane >> 3) & 1);
#pragma unroll
                for (int nq = 0; nq < 4; nq++) {
                    uint32_t t4[4];
                    uint32_t off = (uint32_t)((wn * 64 + nq * 16 + rb2) * 128 + kg * 16);
                    ldsm_x4(t4, sB + swz(off));
                    bf[nq * 2][0] = t4[0]; bf[nq * 2][1] = t4[1];
                    bf[nq * 2 + 1][0] = t4[2]; bf[nq * 2 + 1][1] = t4[3];
                }
            }
#pragma unroll
            for (int mi = 0; mi < 4; mi++)
#pragma unroll
                for (int ni = 0; ni < 8; ni++)
                    mma16816(acc[mi][ni], af[mi], bf[ni]);
        }
    }

    const int gid = lane >> 2, tq = lane & 3;
    if (is_gates) {
#pragma unroll
        for (int mi = 0; mi < 4; mi++) {
#pragma unroll
            for (int ni = 0; ni < 8; ni++) {
                int m = m0 + wm * 64 + mi * 16 + gid;
                int n = n0 + wn * 64 + ni * 8 + tq * 2;
                *(__half2*)&g_gates[(size_t)m * NTOT + n] =
                    __floats2half2_rn(acc[mi][ni][0], acc[mi][ni][1]);
                *(__half2*)&g_gates[(size_t)(m + 8) * NTOT + n] =
                    __floats2half2_rn(acc[mi][ni][2], acc[mi][ni][3]);
            }
        }
    } else {
#pragma unroll
        for (int mi = 0; mi < 4; mi++) {
#pragma unroll
            for (int ni = 0; ni < 8; ni++) {
                int m = m0 + wm * 64 + mi * 16 + gid;
                int n = n0 + wn * 64 + ni * 8 + tq * 2;
                *(__half2*)&g_xresh[(size_t)m * HID + n] =
                    __floats2half2_rn(acc[mi][ni][0], acc[mi][ni][1]);
                *(__half2*)&g_xresh[(size_t)(m + 8) * HID + n] =
                    __floats2half2_rn(acc[mi][ni][2], acc[mi][ni][3]);
            }
        }
    }
}

// ---------------- elementwise LSTM epilogue (4 cells / thread) ----------------
__global__ void lstm_epilogue(const float* __restrict__ c_prev,
                              const float* __restrict__ bg,
                              const float* __restrict__ br,
                              float* __restrict__ out) {
    int hcol = (blockIdx.x * 256 + threadIdx.x) * 4;   // grid.x = HID/1024 = 2
    int b = blockIdx.y;
    const __half* grow = g_gates + (size_t)b * NTOT;

    // 4 halves per gate stream
    uint2 ui = *(const uint2*)&grow[hcol];
    uint2 uf = *(const uint2*)&grow[HID + hcol];
    uint2 uo = *(const uint2*)&grow[2 * HID + hcol];
    uint2 uc = *(const uint2*)&grow[3 * HID + hcol];
    uint2 ux = *(const uint2*)&g_xresh[(size_t)b * HID + hcol];

    float4 bi = *(const float4*)&bg[hcol];
    float4 bf = *(const float4*)&bg[2048 + hcol];
    float4 bo = *(const float4*)&bg[4096 + hcol];
    float4 bc = *(const float4*)&bg[6144 + hcol];
    float4 cp = *(const float4*)&c_prev[(size_t)b * HID + hcol];
    float4 bv = *(const float4*)&br[hcol];

    float pi[4], pf[4], po[4], pc[4], xr[4];
    {
        float2 a0 = __half22float2(*(__half2*)&ui.x), a1 = __half22float2(*(__half2*)&ui.y);
        pi[0] = a0.x; pi[1] = a0.y; pi[2] = a1.x; pi[3] = a1.y;
        float2 b0 = __half22float2(*(__half2*)&uf.x), b1 = __half22float2(*(__half2*)&uf.y);
        pf[0] = b0.x; pf[1] = b0.y; pf[2] = b1.x; pf[3] = b1.y;
        float2 c0 = __half22float2(*(__half2*)&uo.x), c1 = __half22float2(*(__half2*)&uo.y);
        po[0] = c0.x; po[1] = c0.y; po[2] = c1.x; po[3] = c1.y;
        float2 d0 = __half22float2(*(__half2*)&uc.x), d1 = __half22float2(*(__half2*)&uc.y);
        pc[0] = d0.x; pc[1] = d0.y; pc[2] = d1.x; pc[3] = d1.y;
        float2 e0 = __half22float2(*(__half2*)&ux.x), e1 = __half22float2(*(__half2*)&ux.y);
        xr[0] = e0.x; xr[1] = e0.y; xr[2] = e1.x; xr[3] = e1.y;
    }
    const float* bif = &bi.x; const float* bff = &bf.x;
    const float* bof = &bo.x; const float* bcf = &bc.x;
    const float* cpf = &cp.x; const float* bvf = &bv.x;

    float ht[4], ct[4];
#pragma unroll
    for (int e = 0; e < 4; e++) {
        float iv = 1.0f / (1.0f + __expf(-(pi[e] + bif[e])));
        float fv = 1.0f / (1.0f + __expf(-(pf[e] + bff[e])));
        float ov = 1.0f / (1.0f + __expf(-(po[e] + bof[e])));
        float ch = tanhf(pc[e] + bcf[e]);
        ct[e] = fv * cpf[e] + iv * ch;
        ht[e] = ov * tanhf(ct[e]) + xr[e] + bvf[e];
    }

    *(float4*)&out[(size_t)b * HID + hcol] = make_float4(ht[0], ht[1], ht[2], ht[3]);
    *(float4*)&out[(size_t)BATCH * HID + (size_t)b * HID + hcol] =
        make_float4(ct[0], ct[1], ct[2], ct[3]);
}

extern "C" void kernel_launch(void* const* d_in, const int* in_sizes, int n_in,
                              void* d_out, int out_size) {
    const float* x  = (const float*)d_in[0];
    const float* h  = (const float*)d_in[1];
    const float* c  = (const float*)d_in[2];
    const float* Wg = (const float*)d_in[3];
    const float* bg = (const float*)d_in[4];
    const float* Wr = (const float*)d_in[5];
    const float* br = (const float*)d_in[6];
    float* out = (float*)d_out;

    prep_all<<<XH_BLKS + WG_BLKS + WR_BLKS, 256>>>(x, h, Wg, Wr);

    cudaFuncSetAttribute(gemm_all, cudaFuncAttributeMaxDynamicSharedMemorySize, SMEM_BYTES);

    __half* xh;  cudaGetSymbolAddress((void**)&xh,  g_xh);

    // gates CTAs [0, 4096) + residual CTAs [4096, 5120) in one launch
    gemm_all<<<GATES_CTAS + RES_CTAS, THREADS, SMEM_BYTES>>>(xh);

    lstm_epilogue<<<dim3(HID / 1024, BATCH), 256>>>(c, bg, br, out);

    (void)in_sizes; (void)n_in; (void)out_size;
}

// round 17
// speedup vs baseline: 1.0585x; 1.0008x over previous
#include <cuda_runtime.h>
#include <cuda_fp16.h>
#include <cstdint>
#include <math.h>

#define BATCH 8192
#define INDIM 1024
#define HID   2048
#define KTOT  3072
#define NTOT  8192

#define BM 128
#define BN 128
#define BK 64
#define STAGES 3
#define THREADS 128
#define A_BYTES (BM * BK * 2)               // 16384
#define B_BYTES (BN * BK * 2)               // 16384
#define STAGE_BYTES (A_BYTES + B_BYTES)     // 32768
#define SMEM_BYTES (STAGES * STAGE_BYTES)   // 98304 (2 CTAs/SM -> 192KB)

#define GATES_CTAS 4096                     // 64 m-tiles x 64 n-tiles
#define RES_CTAS   1024                     // 64 m-tiles x 16 n-tiles

// prep grid partition (256-thread blocks)
#define XH_BLKS  12288                      // 8192*3072 / (256*8)
#define WG_BLKS  (48 * 32 * 4)              // 6144: 64x64 tiles over [3072,2048] x 4 gates
#define WR_BLKS  (16 * 32)                  // 512:  64x64 tiles over [1024,2048]

__device__ __half g_xh [(size_t)BATCH * KTOT];   // concat(x,h) fp16
__device__ __half g_wt [(size_t)NTOT  * KTOT];   // gates weights, rows = g*HID+h, K-major
__device__ __half g_wrt[(size_t)HID   * INDIM];  // residual weights, K-major
__device__ __half g_gates[(size_t)BATCH * NTOT]; // gate preacts (fp16 scratch)
__device__ __half g_xresh[(size_t)BATCH * HID];  // residual preacts (fp16 scratch)

__device__ __forceinline__ uint32_t smem_u32(const void* p) {
    uint32_t a;
    asm("{ .reg .u64 t; cvta.to.shared.u64 t, %1; cvt.u32.u64 %0, t; }" : "=r"(a) : "l"(p));
    return a;
}
__device__ __forceinline__ uint32_t swz(uint32_t o) { return o ^ ((o >> 3) & 0x70); }
__device__ __forceinline__ void cp16(uint32_t dst, const void* src) {
    asm volatile("cp.async.cg.shared.global [%0], [%1], 16;" :: "r"(dst), "l"(src));
}
#define CP_COMMIT() asm volatile("cp.async.commit_group;" ::: "memory")
#define CP_WAIT(n)  asm volatile("cp.async.wait_group %0;" :: "n"(n) : "memory")

__device__ __forceinline__ void ldsm_x4(uint32_t* d, uint32_t addr) {
    asm volatile("ldmatrix.sync.aligned.m8n8.x4.shared.b16 {%0,%1,%2,%3}, [%4];"
        : "=r"(d[0]), "=r"(d[1]), "=r"(d[2]), "=r"(d[3]) : "r"(addr));
}
__device__ __forceinline__ void mma16816(float* c, const uint32_t* a, const uint32_t* b) {
    asm volatile(
        "mma.sync.aligned.m16n8k16.row.col.f32.f16.f16.f32 "
        "{%0,%1,%2,%3}, {%4,%5,%6,%7}, {%8,%9}, {%0,%1,%2,%3};"
        : "+f"(c[0]), "+f"(c[1]), "+f"(c[2]), "+f"(c[3])
        : "r"(a[0]), "r"(a[1]), "r"(a[2]), "r"(a[3]), "r"(b[0]), "r"(b[1]));
}
// fast tanh: 2*sigmoid(2x)-1, ~1e-6 abs error (well under 3.3e-4 budget)
__device__ __forceinline__ float ftanh(float x) {
    return __fdividef(2.0f, 1.0f + __expf(-2.0f * x)) - 1.0f;
}
__device__ __forceinline__ float fsig(float x) {
    return __fdividef(1.0f, 1.0f + __expf(-x));
}

// ---------------- merged pre-pass (vectorized) ----------------
__global__ void prep_all(const float* __restrict__ x, const float* __restrict__ h,
                         const float* __restrict__ Wg, const float* __restrict__ Wr) {
    __shared__ float t[64][65];
    int bid = blockIdx.x;
    int tid = threadIdx.x;

    if (bid < XH_BLKS) {
        // concat(x,h) -> fp16, 8 elems / thread, 16B packed store
        size_t idx = ((size_t)bid * 256 + tid) * 8;
        int b = (int)(idx / KTOT);
        int k = (int)(idx % KTOT);
        const float* src = (k < INDIM) ? (x + (size_t)b * INDIM + k)
                                       : (h + (size_t)b * HID + (k - INDIM));
        float4 v0 = *(const float4*)src;
        float4 v1 = *(const float4*)(src + 4);
        __half2 o[4];
        o[0] = __floats2half2_rn(v0.x, v0.y);
        o[1] = __floats2half2_rn(v0.z, v0.w);
        o[2] = __floats2half2_rn(v1.x, v1.y);
        o[3] = __floats2half2_rn(v1.z, v1.w);
        *(uint4*)&g_xh[idx] = *(uint4*)o;
        return;
    }

    // 64x64 transpose tiles
    const float* src;
    __half* dstbase;
    int k0, h0, dst_ld;
    if (bid < XH_BLKS + WG_BLKS) {
        int tb = bid - XH_BLKS;
        int kb = tb % 48, hb = (tb / 48) % 32, g = tb / (48 * 32);
        k0 = kb * 64; h0 = hb * 64;
        src = Wg + ((size_t)g * KTOT + k0) * HID + h0;
        dstbase = g_wt + (size_t)g * HID * KTOT;
        dst_ld = KTOT;
    } else {
        int tb = bid - XH_BLKS - WG_BLKS;
        int kb = tb % 16, hb = tb / 16;
        k0 = kb * 64; h0 = hb * 64;
        src = Wr + (size_t)k0 * HID + h0;
        dstbase = g_wrt;
        dst_ld = INDIM;
    }

    {
        int col = tid & 63;
        int rb = tid >> 6;          // 0..3
#pragma unroll
        for (int i = 0; i < 16; i++) {
            int row = i * 4 + rb;
            t[row][col] = src[(size_t)row * HID + col];
        }
    }
    __syncthreads();

    {
        int a = tid & 31;           // k-pair index: k = 2a, 2a+1
        int hb2 = tid >> 5;         // 0..7
#pragma unroll
        for (int i = 0; i < 8; i++) {
            int hh = i * 8 + hb2;
            __half2 v = __floats2half2_rn(t[2 * a][hh], t[2 * a + 1][hh]);
            *(__half2*)&dstbase[(size_t)(h0 + hh) * dst_ld + k0 + 2 * a] = v;
        }
    }
}

// ---------------- combined GEMM: gates CTAs + residual CTAs ----------------
__device__ __forceinline__ void load_stage(uint32_t sA, uint32_t sB,
                                           const __half* __restrict__ A,
                                           const __half* __restrict__ Bw,
                                           int m0, int n0, int k0,
                                           int lda, int ldb, int tid) {
#pragma unroll
    for (int it = 0; it < 8; it++) {             // A: 128 rows x 8 x 16B
        int i = tid + it * THREADS;
        int r = i >> 3, cg = i & 7;
        uint32_t sw = swz((uint32_t)(r * 128 + cg * 16));
        cp16(sA + sw, A + (size_t)(m0 + r) * lda + k0 + cg * 8);
    }
#pragma unroll
    for (int it = 0; it < 8; it++) {             // B: 128 rows x 8 x 16B
        int i = tid + it * THREADS;
        int r = i >> 3, cg = i & 7;
        uint32_t sw = swz((uint32_t)(r * 128 + cg * 16));
        cp16(sB + sw, Bw + (size_t)(n0 + r) * ldb + k0 + cg * 8);
    }
}

__global__ void __launch_bounds__(THREADS, 2)
gemm_all(const __half* __restrict__ A) {
    extern __shared__ char smem[];
    uint32_t sb = smem_u32(smem);
    const int tid = threadIdx.x, lane = tid & 31, wid = tid >> 5;
    const int wm = wid & 1;                 // 2 warps along M (64 rows each)
    const int wn = wid >> 1;                // 2 warps along N (64 cols each)

    const int bid = blockIdx.x;
    const bool is_gates = (bid < GATES_CTAS);
    int m0, n0, K, ldb;
    const __half* Bw;
    if (is_gates) {
        m0 = (bid & 63) * BM;               // m fastest -> L2 weight reuse per wave
        n0 = (bid >> 6) * BN;
        K = KTOT; ldb = KTOT; Bw = g_wt;
    } else {
        int rb = bid - GATES_CTAS;
        m0 = (rb & 63) * BM;
        n0 = (rb >> 6) * BN;                // 16 n-tiles
        K = INDIM; ldb = INDIM; Bw = g_wrt;
    }
    const int lda = KTOT;
    const int nch = K / BK;

    float acc[4][8][4];
#pragma unroll
    for (int mi = 0; mi < 4; mi++)
#pragma unroll
        for (int ni = 0; ni < 8; ni++)
#pragma unroll
            for (int e = 0; e < 4; e++) acc[mi][ni][e] = 0.0f;

#pragma unroll
    for (int s = 0; s < STAGES - 1; s++) {
        load_stage(sb + s * STAGE_BYTES, sb + s * STAGE_BYTES + A_BYTES,
                   A, Bw, m0, n0, s * BK, lda, ldb, tid);
        CP_COMMIT();
    }

    for (int c = 0; c < nch; c++) {
        CP_WAIT(STAGES - 2);
        __syncthreads();

        int cl = c + STAGES - 1;
        if (cl < nch) {
            int s = cl % STAGES;
            load_stage(sb + s * STAGE_BYTES, sb + s * STAGE_BYTES + A_BYTES,
                       A, Bw, m0, n0, cl * BK, lda, ldb, tid);
        }
        CP_COMMIT();

        uint32_t sA = sb + (c % STAGES) * STAGE_BYTES;
        uint32_t sB = sA + A_BYTES;

#pragma unroll
        for (int ks = 0; ks < 4; ks++) {
            uint32_t af[4][4];
            {
                int ra = lane & 15;
                int kg = ks * 2 + (lane >> 4);
#pragma unroll
                for (int mi = 0; mi < 4; mi++) {
                    uint32_t off = (uint32_t)((wm * 64 + mi * 16 + ra) * 128 + kg * 16);
                    ldsm_x4(af[mi], sA + swz(off));
                }
            }
            uint32_t bf[8][2];
            {
                int rb2 = (lane & 7) + ((lane >> 4) << 3);
                int kg = ks * 2 + ((lane >> 3) & 1);
#pragma unroll
                for (int nq = 0; nq < 4; nq++) {
                    uint32_t t4[4];
                    uint32_t off = (uint32_t)((wn * 64 + nq * 16 + rb2) * 128 + kg * 16);
                    ldsm_x4(t4, sB + swz(off));
                    bf[nq * 2][0] = t4[0]; bf[nq * 2][1] = t4[1];
                    bf[nq * 2 + 1][0] = t4[2]; bf[nq * 2 + 1][1] = t4[3];
                }
            }
#pragma unroll
            for (int mi = 0; mi < 4; mi++)
#pragma unroll
                for (int ni = 0; ni < 8; ni++)
                    mma16816(acc[mi][ni], af[mi], bf[ni]);
        }
    }

    // PDL: signal dependents (epilogue) may be scheduled; stores still ahead,
    // epilogue's griddepcontrol.wait orders its gate reads after our completion.
    asm volatile("griddepcontrol.launch_dependents;");

    const int gid = lane >> 2, tq = lane & 3;
    if (is_gates) {
#pragma unroll
        for (int mi = 0; mi < 4; mi++) {
#pragma unroll
            for (int ni = 0; ni < 8; ni++) {
                int m = m0 + wm * 64 + mi * 16 + gid;
                int n = n0 + wn * 64 + ni * 8 + tq * 2;
                *(__half2*)&g_gates[(size_t)m * NTOT + n] =
                    __floats2half2_rn(acc[mi][ni][0], acc[mi][ni][1]);
                *(__half2*)&g_gates[(size_t)(m + 8) * NTOT + n] =
                    __floats2half2_rn(acc[mi][ni][2], acc[mi][ni][3]);
            }
        }
    } else {
#pragma unroll
        for (int mi = 0; mi < 4; mi++) {
#pragma unroll
            for (int ni = 0; ni < 8; ni++) {
                int m = m0 + wm * 64 + mi * 16 + gid;
                int n = n0 + wn * 64 + ni * 8 + tq * 2;
                *(__half2*)&g_xresh[(size_t)m * HID + n] =
                    __floats2half2_rn(acc[mi][ni][0], acc[mi][ni][1]);
                *(__half2*)&g_xresh[(size_t)(m + 8) * HID + n] =
                    __floats2half2_rn(acc[mi][ni][2], acc[mi][ni][3]);
            }
        }
    }
}

// ---------------- elementwise LSTM epilogue (4 cells / thread, PDL) ----------------
__global__ void lstm_epilogue(const float* __restrict__ c_prev,
                              const float* __restrict__ bg,
                              const float* __restrict__ br,
                              float* __restrict__ out) {
    int hcol = (blockIdx.x * 256 + threadIdx.x) * 4;   // grid.x = HID/1024 = 2
    int b = blockIdx.y;

    // ---- independent prefetch (inputs only; race-free vs primary grid) ----
    float4 bi = *(const float4*)&bg[hcol];
    float4 bf = *(const float4*)&bg[2048 + hcol];
    float4 bo = *(const float4*)&bg[4096 + hcol];
    float4 bc = *(const float4*)&bg[6144 + hcol];
    float4 cp = *(const float4*)&c_prev[(size_t)b * HID + hcol];
    float4 bv = *(const float4*)&br[hcol];

    // ---- wait for GEMM grid completion before touching its outputs ----
    asm volatile("griddepcontrol.wait;" ::: "memory");

    const __half* grow = g_gates + (size_t)b * NTOT;
    uint2 ui = *(const uint2*)&grow[hcol];
    uint2 uf = *(const uint2*)&grow[HID + hcol];
    uint2 uo = *(const uint2*)&grow[2 * HID + hcol];
    uint2 uc = *(const uint2*)&grow[3 * HID + hcol];
    uint2 ux = *(const uint2*)&g_xresh[(size_t)b * HID + hcol];

    float pi[4], pf[4], po[4], pc[4], xr[4];
    {
        float2 a0 = __half22float2(*(__half2*)&ui.x), a1 = __half22float2(*(__half2*)&ui.y);
        pi[0] = a0.x; pi[1] = a0.y; pi[2] = a1.x; pi[3] = a1.y;
        float2 b0 = __half22float2(*(__half2*)&uf.x), b1 = __half22float2(*(__half2*)&uf.y);
        pf[0] = b0.x; pf[1] = b0.y; pf[2] = b1.x; pf[3] = b1.y;
        float2 c0 = __half22float2(*(__half2*)&uo.x), c1 = __half22float2(*(__half2*)&uo.y);
        po[0] = c0.x; po[1] = c0.y; po[2] = c1.x; po[3] = c1.y;
        float2 d0 = __half22float2(*(__half2*)&uc.x), d1 = __half22float2(*(__half2*)&uc.y);
        pc[0] = d0.x; pc[1] = d0.y; pc[2] = d1.x; pc[3] = d1.y;
        float2 e0 = __half22float2(*(__half2*)&ux.x), e1 = __half22float2(*(__half2*)&ux.y);
        xr[0] = e0.x; xr[1] = e0.y; xr[2] = e1.x; xr[3] = e1.y;
    }
    const float* bif = &bi.x; const float* bff = &bf.x;
    const float* bof = &bo.x; const float* bcf = &bc.x;
    const float* cpf = &cp.x; const float* bvf = &bv.x;

    float ht[4], ct[4];
#pragma unroll
    for (int e = 0; e < 4; e++) {
        float iv = fsig(pi[e] + bif[e]);
        float fv = fsig(pf[e] + bff[e]);
        float ov = fsig(po[e] + bof[e]);
        float ch = ftanh(pc[e] + bcf[e]);
        ct[e] = fv * cpf[e] + iv * ch;
        ht[e] = ov * ftanh(ct[e]) + xr[e] + bvf[e];
    }

    *(float4*)&out[(size_t)b * HID + hcol] = make_float4(ht[0], ht[1], ht[2], ht[3]);
    *(float4*)&out[(size_t)BATCH * HID + (size_t)b * HID + hcol] =
        make_float4(ct[0], ct[1], ct[2], ct[3]);
}

extern "C" void kernel_launch(void* const* d_in, const int* in_sizes, int n_in,
                              void* d_out, int out_size) {
    const float* x  = (const float*)d_in[0];
    const float* h  = (const float*)d_in[1];
    const float* c  = (const float*)d_in[2];
    const float* Wg = (const float*)d_in[3];
    const float* bg = (const float*)d_in[4];
    const float* Wr = (const float*)d_in[5];
    const float* br = (const float*)d_in[6];
    float* out = (float*)d_out;

    prep_all<<<XH_BLKS + WG_BLKS + WR_BLKS, 256>>>(x, h, Wg, Wr);

    cudaFuncSetAttribute(gemm_all, cudaFuncAttributeMaxDynamicSharedMemorySize, SMEM_BYTES);

    __half* xh;  cudaGetSymbolAddress((void**)&xh,  g_xh);

    // gates CTAs [0, 4096) + residual CTAs [4096, 5120) in one launch
    gemm_all<<<GATES_CTAS + RES_CTAS, THREADS, SMEM_BYTES>>>(xh);

    // epilogue with PDL edge: may be scheduled while gemm_all drains;
    // griddepcontrol.wait inside orders gate reads after gemm completion.
    {
        cudaLaunchConfig_t cfg = {};
        cfg.gridDim = dim3(HID / 1024, BATCH);
        cfg.blockDim = dim3(256);
        cudaLaunchAttribute at[1];
        at[0].id = cudaLaunchAttributeProgrammaticStreamSerialization;
        at[0].val.programmaticStreamSerializationAllowed = 1;
        cfg.attrs = at;
        cfg.numAttrs = 1;
        cudaLaunchKernelEx(&cfg, lstm_epilogue, c, bg, br, out);
    }

    (void)in_sizes; (void)n_in; (void)out_size;
}